// round 1
// baseline (speedup 1.0000x reference)
#include <cuda_runtime.h>

#define N_NODES 100000
#define N_EDGES 800000
#define C 128

// Scratch (allocation-free per harness rules): per-node dot products.
__device__ float g_s[N_NODES];   // x_0[i] . att[:C]
__device__ float g_t[N_NODES];   // x_0[i] . att[C:]
__device__ int   g_idx_is64;     // 1 if index buffers are int64, 0 if int32

// Detect index dtype: if the buffer holds int64 values in [0, 100000),
// every odd 32-bit word (little-endian high half) is zero. For int32 data,
// 64 consecutive odd-position random indices being all zero is ~impossible.
__global__ void detect_idx_dtype_kernel(const unsigned int* __restrict__ src32) {
    unsigned int acc = 0;
#pragma unroll
    for (int i = 0; i < 64; ++i) acc |= src32[2 * i + 1];
    g_idx_is64 = (acc == 0u) ? 1 : 0;
}

// Warp-per-node: coalesced 512B row load, two dot products, butterfly reduce.
__global__ void __launch_bounds__(256) node_dot_kernel(
    const float* __restrict__ x, const float* __restrict__ att) {
    int warp = (blockIdx.x * blockDim.x + threadIdx.x) >> 5;
    int lane = threadIdx.x & 31;
    if (warp >= N_NODES) return;

    const float4 xv = reinterpret_cast<const float4*>(x + (size_t)warp * C)[lane];
    const float4 ws = reinterpret_cast<const float4*>(att)[lane];
    const float4 wt = reinterpret_cast<const float4*>(att + C)[lane];

    float s = xv.x * ws.x + xv.y * ws.y + xv.z * ws.z + xv.w * ws.w;
    float t = xv.x * wt.x + xv.y * wt.y + xv.z * wt.z + xv.w * wt.w;

#pragma unroll
    for (int o = 16; o > 0; o >>= 1) {
        s += __shfl_xor_sync(0xffffffffu, s, o);
        t += __shfl_xor_sync(0xffffffffu, t, o);
    }
    if (lane == 0) {
        g_s[warp] = s;
        g_t[warp] = t;
    }
}

// 1 thread/edge: coalesced index loads, L2-resident scalar gathers, relu, store.
__global__ void __launch_bounds__(256) edge_kernel(
    const void* __restrict__ src, const void* __restrict__ tgt,
    float* __restrict__ out) {
    int e = blockIdx.x * blockDim.x + threadIdx.x;
    if (e >= N_EDGES) return;

    int si, ti;
    if (g_idx_is64) {
        si = (int)reinterpret_cast<const long long*>(src)[e];
        ti = (int)reinterpret_cast<const long long*>(tgt)[e];
    } else {
        si = reinterpret_cast<const int*>(src)[e];
        ti = reinterpret_cast<const int*>(tgt)[e];
    }
    float v = g_s[si] + g_t[ti];
    out[e] = fmaxf(v, 0.0f);
}

extern "C" void kernel_launch(void* const* d_in, const int* in_sizes, int n_in,
                              void* d_out, int out_size) {
    const float* x_0 = (const float*)d_in[0];
    const void*  src = d_in[1];
    const void*  tgt = d_in[2];
    const float* att = (const float*)d_in[3];
    float* out = (float*)d_out;

    detect_idx_dtype_kernel<<<1, 1>>>((const unsigned int*)src);

    // warp per node, 8 warps per 256-thread block
    int node_blocks = (N_NODES + 7) / 8;
    node_dot_kernel<<<node_blocks, 256>>>(x_0, att);

    int edge_blocks = (N_EDGES + 255) / 256;
    edge_kernel<<<edge_blocks, 256>>>(src, tgt, out);
}